// round 16
// baseline (speedup 1.0000x reference)
#include <cuda_runtime.h>
#include <cuda_bf16.h>
#include <cuda_fp16.h>
#include <cstdint>
#include <math.h>

#define EMBD 1536
#define HID 1536
#define KH (HID/2)                /* 768 packed k-pairs */
#define VOCAB 32000
#define NLAYERS 2
#define SEQ 64
#define BATCH 32
#define NROW (SEQ*BATCH)          /* 2048 */
#define BH (BATCH*HID)            /* 49152 */
#define NBLK 144
#define SCL 2048.0f
#define ISCL (1.0f/2048.0f)

// ---------------- device scratch ----------------
__device__ uint32_t g_wf[9][HID][KH];                 // recurrent weights fp16x2 single plane [n][k2]
__device__ uint32_t g_wxp[3][2][HID][KH];             // xproj weights bf16 hi/lo planes
__device__ uint32_t g_wo16[VOCAB][KH];                // Wout fp16x2 [v][k2]
__device__ uint32_t g_x0sp[2][NROW][KH];              // embeddings bf16 hi/lo
__device__ uint32_t g_X16[NROW][KH];                  // layer-1 outputs fp16 single plane
__device__ uint32_t g_hsp[2][NLAYERS][2][BATCH][KH];  // hidden fp16 hi + fp16 scaled-lo (ping-pong)
__device__ float    g_hbuf[2][NLAYERS*BH];            // fp32 hidden (ping-pong)
__device__ float    g_l0x[3*(size_t)NROW*HID];        // layer0 x-side projections
__device__ float    g_stage[9][(size_t)BH];           // pre-activations

__device__ unsigned g_bar_count = 0;
__device__ volatile unsigned g_bar_gen = 0;

struct P {
  const int* tok; const float* hidden; const float* emb;
  const float *Wir,*bir,*Whr,*bhr,*Wiu,*biu,*Whu,*bhu,*Wic,*bic,*Whc,*bhc,*Wout,*bout;
};

__device__ __forceinline__ float sigf(float x){ return 1.f/(1.f+expf(-x)); }

__device__ __forceinline__ uint32_t packbf(float a, float b){
  __nv_bfloat162 t; t.x = __float2bfloat16_rn(a); t.y = __float2bfloat16_rn(b);
  return *reinterpret_cast<uint32_t*>(&t);
}
__device__ __forceinline__ void split2(float a, float b, uint32_t& hi, uint32_t& lo){
  __nv_bfloat16 ha = __float2bfloat16_rn(a), hb = __float2bfloat16_rn(b);
  hi = packbf(__bfloat162float(ha), __bfloat162float(hb));
  lo = packbf(a - __bfloat162float(ha), b - __bfloat162float(hb));
}
__device__ __forceinline__ uint32_t packh(float a, float b){
  __half2 t = __floats2half2_rn(a, b);
  return *reinterpret_cast<uint32_t*>(&t);
}
__device__ __forceinline__ void splitH(float a, float b, uint32_t& hi, uint32_t& lo, float s){
  __half ha = __float2half_rn(a), hb = __float2half_rn(b);
  hi = packh(__half2float(ha), __half2float(hb));
  lo = packh((a - __half2float(ha))*s, (b - __half2float(hb))*s);
}
__device__ __forceinline__ void mma_bf16(float c[4],
    uint32_t a0,uint32_t a1,uint32_t a2,uint32_t a3, uint32_t b0,uint32_t b1){
  asm volatile(
    "mma.sync.aligned.m16n8k16.row.col.f32.bf16.bf16.f32 "
    "{%0,%1,%2,%3},{%4,%5,%6,%7},{%8,%9},{%0,%1,%2,%3};"
    : "+f"(c[0]),"+f"(c[1]),"+f"(c[2]),"+f"(c[3])
    : "r"(a0),"r"(a1),"r"(a2),"r"(a3),"r"(b0),"r"(b1));
}
__device__ __forceinline__ void mma_f16(float c[4],
    uint32_t a0,uint32_t a1,uint32_t a2,uint32_t a3, uint32_t b0,uint32_t b1){
  asm volatile(
    "mma.sync.aligned.m16n8k16.row.col.f32.f16.f16.f32 "
    "{%0,%1,%2,%3},{%4,%5,%6,%7},{%8,%9},{%0,%1,%2,%3};"
    : "+f"(c[0]),"+f"(c[1]),"+f"(c[2]),"+f"(c[3])
    : "r"(a0),"r"(a1),"r"(a2),"r"(a3),"r"(b0),"r"(b1));
}
__device__ __forceinline__ void ldsm4(uint32_t* r, uint32_t addr){
  asm volatile("ldmatrix.sync.aligned.m8n8.x4.shared.b16 {%0,%1,%2,%3}, [%4];"
    : "=r"(r[0]),"=r"(r[1]),"=r"(r[2]),"=r"(r[3]) : "r"(addr));
}
__device__ __forceinline__ uint32_t smem_u32(const void* p){
  uint32_t a;
  asm("{ .reg .u64 t; cvta.to.shared.u64 t, %1; cvt.u32.u64 %0, t; }" : "=r"(a) : "l"(p));
  return a;
}

// ---------------- grid barrier ----------------
__device__ __forceinline__ void gridbar(){
  __syncthreads();
  if (threadIdx.x==0){
    __threadfence();
    unsigned gen = g_bar_gen;
    if (atomicInc(&g_bar_count, NBLK-1) == (unsigned)(NBLK-1)){
      g_bar_gen = gen+1;
    } else {
      while (g_bar_gen == gen) {}
    }
    __threadfence();
  }
  __syncthreads();
}

// ---------------- one-time weight split ----------------
// mats 0-8 (recurrent): fp16 single plane; mats 9-11 (xproj): bf16 hi/lo
__global__ __launch_bounds__(256) void split_weights(P p){
  int mat = blockIdx.z;
  size_t HH = (size_t)HID*HID;
  const float* Wm;
  switch(mat){
    case 0: Wm=p.Whr;    break; case 1: Wm=p.Whu;    break; case 2:  Wm=p.Whc;    break;
    case 3: Wm=p.Whr+HH; break; case 4: Wm=p.Whu+HH; break; case 5:  Wm=p.Whc+HH; break;
    case 6: Wm=p.Wir+HH; break; case 7: Wm=p.Wiu+HH; break; case 8:  Wm=p.Wic+HH; break;
    case 9: Wm=p.Wir;    break; case 10:Wm=p.Wiu;    break; default: Wm=p.Wic;    break;
  }
  __shared__ float tile[32][33];
  int kc = blockIdx.y*32, n0 = blockIdx.x*32;
  int t = threadIdx.x;
  #pragma unroll
  for (int i=0;i<4;i++){
    int idx = t + i*256; int ky = idx>>5, nx = idx&31;
    tile[ky][nx] = Wm[(size_t)(kc+ky)*HID + n0+nx];
  }
  __syncthreads();
  #pragma unroll
  for (int i=0;i<2;i++){
    int slot = t + i*256; int ny = slot>>4, kx2 = slot&15;
    float a = tile[kx2*2][ny], b = tile[kx2*2+1][ny];
    if (mat < 9){
      g_wf[mat][n0+ny][(kc>>1)+kx2] = packh(a, b);
    } else {
      uint32_t hi, lo; split2(a, b, hi, lo);
      g_wxp[mat-9][0][n0+ny][(kc>>1)+kx2] = hi;
      g_wxp[mat-9][1][n0+ny][(kc>>1)+kx2] = lo;
    }
  }
}

// ---------------- Wout -> fp16 [v][k2] ----------------
__global__ __launch_bounds__(256) void split_wout(P p){
  __shared__ float tile[32][33];
  int kc = blockIdx.y*32, v0 = blockIdx.x*32;
  int t = threadIdx.x;
  #pragma unroll
  for (int i=0;i<4;i++){
    int idx = t + i*256; int ky = idx>>5, vx = idx&31;
    tile[ky][vx] = p.Wout[(size_t)(kc+ky)*VOCAB + v0+vx];
  }
  __syncthreads();
  #pragma unroll
  for (int i=0;i<2;i++){
    int slot = t + i*256; int vy = slot>>4, kx2 = slot&15;
    g_wo16[v0+vy][(kc>>1)+kx2] = packh(tile[kx2*2][vy], tile[kx2*2+1][vy]);
  }
}

// ---------------- embed + scale -> bf16 split ----------------
__global__ void embed_split(P p){
  int idx = blockIdx.x*blockDim.x + threadIdx.x;
  if (idx >= NROW*(EMBD/4)) return;
  int row = idx/(EMBD/4), e4 = idx%(EMBD/4);
  float4 v = ((const float4*)p.emb)[(size_t)p.tok[row]*(EMBD/4)+e4];
  float s = sqrtf((float)EMBD);
  uint32_t h0,l0,h1,l1;
  split2(v.x*s, v.y*s, h0, l0);
  split2(v.z*s, v.w*s, h1, l1);
  g_x0sp[0][row][e4*2]   = h0; g_x0sp[0][row][e4*2+1] = h1;
  g_x0sp[1][row][e4*2]   = l0; g_x0sp[1][row][e4*2+1] = l1;
}

__global__ void init_h_kernel(P p){
  int i = blockIdx.x*blockDim.x + threadIdx.x;
  if (i >= NLAYERS*BH/2) return;
  int e = i*2;
  float v0 = p.hidden[e], v1 = p.hidden[e+1];
  g_hbuf[0][e] = v0; g_hbuf[0][e+1] = v1;
  int layer = e / BH, rem = e % BH;
  int r = rem / HID, k = rem % HID;
  uint32_t hi, lo; splitH(v0, v1, hi, lo, SCL);
  g_hsp[0][layer][0][r][k>>1] = hi;
  g_hsp[0][layer][1][r][k>>1] = lo;
}
__global__ void copy_h_kernel(float* out){
  int i = blockIdx.x*blockDim.x + threadIdx.x;
  if (i < NLAYERS*BH) out[i] = g_hbuf[0][i];
}

// ---------------- persistent recurrence: fp16 2-pass ----------------
__global__ __launch_bounds__(256) void rec_persistent(P p){
  __shared__ union SMu {
    struct { uint32_t A[2][2][32][20]; uint32_t W[2][64][20]; } p1;
    struct { uint32_t A[2][2][2][32][20]; uint32_t W[2][2][32][20]; } p2;
    float red[128*8];
  } sm;

  int blk = blockIdx.x, tid = threadIdx.x;
  int warp = tid>>5, lane = tid&31, gid = lane>>2, tig = lane&3;
  int lr16 = lane&15, lws = (lane>>4)&1;
  int wr8 = lane&7,  ws4 = (lane>>3)&3;

  for (int t=0; t<SEQ; t++){
    int cb = t&1, nb = cb^1;

    // ======== phase 1 ========
    {
      int mat = blk/24, n0 = (blk%24)*64;
      int layer = mat/3;
      const uint32_t* Ah = &g_hsp[cb][layer][0][0][0];
      const uint32_t* Al = &g_hsp[cb][layer][1][0][0];
      float accH[2][4] = {}, accL[2][4] = {};
      int c0 = warp*8;
      uint32_t aBase = smem_u32(&sm.p1.A[0][0][0][0]);
      uint32_t wBase = smem_u32(&sm.p1.W[0][0][0]);

      int a_pl = tid>>7, a_row = (tid>>2)&31, a_q = tid&3;
      const uint32_t* Aside = a_pl ? Al : Ah;
      int w_col = tid>>2, w_q = tid&3;
      uint4 pa, pw;
      auto ld = [&](int kc2){
        pa = *(const uint4*)&Aside[a_row*KH + kc2 + a_q*4];
        pw = *(const uint4*)&g_wf[mat][n0+w_col][kc2 + w_q*4];
      };
      auto stbuf = [&](int b){
        *(uint4*)&sm.p1.A[b][a_pl][a_row][a_q*4] = pa;
        *(uint4*)&sm.p1.W[b][w_col][w_q*4] = pw;
      };
      ld(0); stbuf(0); __syncthreads();
      for (int s=0; s<48; s++){
        int cur = s&1;
        if (s<47) ld((s+1)*16);
        uint32_t af[2][2][2][4];
        #pragma unroll
        for (int pl=0;pl<2;pl++)
          #pragma unroll
          for (int mt=0;mt<2;mt++)
            #pragma unroll
            for (int ks=0;ks<2;ks++)
              ldsm4(af[pl][mt][ks],
                aBase + 4u*((uint32_t)(((cur*2+pl)*32) + mt*16 + lr16)*20u + ks*8 + lws*4));
        uint32_t wb[4];
        ldsm4(wb, wBase + 4u*((uint32_t)(cur*64 + c0 + wr8)*20u + ws4*4));
        #pragma unroll
        for (int ks=0;ks<2;ks++){
          uint32_t b0=wb[ks*2], b1=wb[ks*2+1];
          #pragma unroll
          for (int mt=0;mt<2;mt++){
            mma_f16(accH[mt], af[0][mt][ks][0],af[0][mt][ks][1],af[0][mt][ks][2],af[0][mt][ks][3], b0,b1);
            mma_f16(accL[mt], af[1][mt][ks][0],af[1][mt][ks][1],af[1][mt][ks][2],af[1][mt][ks][3], b0,b1);
          }
        }
        if (s<47){ stbuf(cur^1); __syncthreads(); }
      }
      int col = n0 + warp*8 + tig*2;
      #pragma unroll
      for (int mt=0; mt<2; mt++){
        int r = mt*16+gid;
        g_stage[mat][(size_t)r*HID+col]       = accH[mt][0] + accL[mt][0]*ISCL;
        g_stage[mat][(size_t)r*HID+col+1]     = accH[mt][1] + accL[mt][1]*ISCL;
        g_stage[mat][(size_t)(r+8)*HID+col]   = accH[mt][2] + accL[mt][2]*ISCL;
        g_stage[mat][(size_t)(r+8)*HID+col+1] = accH[mt][3] + accL[mt][3]*ISCL;
      }
    }
    gridbar();

    // ======== G0 ========
    {
      int pr = blk*256 + tid;
      if (pr < BH/2){
        int r = pr/(HID/2), jc = (pr%(HID/2))*2;
        size_t trow = (size_t)t*BATCH + r;
        float hn[2];
        #pragma unroll
        for (int e=0;e<2;e++){
          int col = jc+e;
          float xr = g_l0x[0*(size_t)NROW*HID + trow*HID + col];
          float xu = g_l0x[1*(size_t)NROW*HID + trow*HID + col];
          float xc = g_l0x[2*(size_t)NROW*HID + trow*HID + col];
          float hr = g_stage[0][(size_t)r*HID+col];
          float hu = g_stage[1][(size_t)r*HID+col];
          float hc = g_stage[2][(size_t)r*HID+col];
          float rr = sigf(xr + p.bir[col] + hr + p.bhr[col]);
          float uu = sigf(xu + p.biu[col] + hu + p.bhu[col]);
          float cv = tanhf(xc + p.bic[col] + rr*(hc + p.bhc[col]));
          float h  = g_hbuf[cb][(size_t)r*HID+col];
          hn[e] = (1.f-uu)*cv + uu*h;
          g_hbuf[nb][(size_t)r*HID+col] = hn[e];
        }
        uint32_t hi, lo; splitH(hn[0], hn[1], hi, lo, SCL);
        g_hsp[nb][0][0][r][jc>>1] = hi;
        g_hsp[nb][0][1][r][jc>>1] = lo;
      }
    }
    gridbar();

    // ======== phase 2 ========
    {
      int mat = 6 + blk/48, n0 = (blk%48)*32;
      const uint32_t* Ah = &g_hsp[nb][0][0][0][0];
      const uint32_t* Al = &g_hsp[nb][0][1][0][0];
      float accH[2][4] = {}, accL[2][4] = {};
      int half = warp>>2, cg = warp&3;
      int c0 = cg*8;
      uint32_t aBase = smem_u32(&sm.p2.A[0][0][0][0][0]);
      uint32_t wBase = smem_u32(&sm.p2.W[0][0][0][0]);

      uint4 pa[2], pw;
      auto ld2 = [&](int s16){
        #pragma unroll
        for (int i=0;i<2;i++){
          int idx = tid + i*256;
          int pl = idx>>8, hf = (idx>>7)&1, row = (idx>>2)&31, q = idx&3;
          const uint32_t* As = pl ? Al : Ah;
          pa[i] = *(const uint4*)&As[row*KH + hf*(KH/2) + s16 + q*4];
        }
        int hf = tid>>7, row = (tid>>2)&31, q = tid&3;
        pw = *(const uint4*)&g_wf[mat][n0+row][hf*(KH/2) + s16 + q*4];
      };
      auto stbuf2 = [&](int b){
        #pragma unroll
        for (int i=0;i<2;i++){
          int idx = tid + i*256;
          int pl = idx>>8, hf = (idx>>7)&1, row = (idx>>2)&31, q = idx&3;
          *(uint4*)&sm.p2.A[b][pl][hf][row][q*4] = pa[i];
        }
        int hf = tid>>7, row = (tid>>2)&31, q = tid&3;
        *(uint4*)&sm.p2.W[b][hf][row][q*4] = pw;
      };
      ld2(0); stbuf2(0); __syncthreads();
      for (int s=0; s<24; s++){
        int cur = s&1;
        if (s<23) ld2((s+1)*16);
        uint32_t af[2][2][2][4];
        #pragma unroll
        for (int pl=0;pl<2;pl++)
          #pragma unroll
          for (int mt=0;mt<2;mt++)
            #pragma unroll
            for (int ks=0;ks<2;ks++)
              ldsm4(af[pl][mt][ks],
                aBase + 4u*((uint32_t)((((cur*2+pl)*2+half)*32) + mt*16 + lr16)*20u + ks*8 + lws*4));
        uint32_t wb[4];
        ldsm4(wb, wBase + 4u*((uint32_t)((cur*2+half)*32 + c0 + wr8)*20u + ws4*4));
        #pragma unroll
        for (int ks=0;ks<2;ks++){
          uint32_t b0=wb[ks*2], b1=wb[ks*2+1];
          #pragma unroll
          for (int mt=0;mt<2;mt++){
            mma_f16(accH[mt], af[0][mt][ks][0],af[0][mt][ks][1],af[0][mt][ks][2],af[0][mt][ks][3], b0,b1);
            mma_f16(accL[mt], af[1][mt][ks][0],af[1][mt][ks][1],af[1][mt][ks][2],af[1][mt][ks][3], b0,b1);
          }
        }
        if (s<23){ stbuf2(cur^1); __syncthreads(); }
      }
      float acc[2][4];
      #pragma unroll
      for (int mt=0;mt<2;mt++)
        #pragma unroll
        for (int f=0;f<4;f++) acc[mt][f] = accH[mt][f] + accL[mt][f]*ISCL;
      __syncthreads();
      if (half==1){
        #pragma unroll
        for (int mt=0; mt<2; mt++)
          #pragma unroll
          for (int f=0; f<4; f++)
            sm.red[(tid&127)*8 + mt*4+f] = acc[mt][f];
      }
      __syncthreads();
      if (half==0){
        #pragma unroll
        for (int mt=0; mt<2; mt++)
          #pragma unroll
          for (int f=0; f<4; f++)
            acc[mt][f] += sm.red[(tid&127)*8 + mt*4+f];
        int col = n0 + cg*8 + tig*2;
        #pragma unroll
        for (int mt=0; mt<2; mt++){
          int r = mt*16+gid;
          g_stage[mat][(size_t)r*HID+col]       = acc[mt][0];
          g_stage[mat][(size_t)r*HID+col+1]     = acc[mt][1];
          g_stage[mat][(size_t)(r+8)*HID+col]   = acc[mt][2];
          g_stage[mat][(size_t)(r+8)*HID+col+1] = acc[mt][3];
        }
      }
    }
    gridbar();

    // ======== G1 ========
    {
      int pr = blk*256 + tid;
      if (pr < BH/2){
        int r = pr/(HID/2), jc = (pr%(HID/2))*2;
        size_t trow = (size_t)t*BATCH + r;
        float hn[2];
        #pragma unroll
        for (int e=0;e<2;e++){
          int col = jc+e;
          float xr = g_stage[6][(size_t)r*HID+col];
          float xu = g_stage[7][(size_t)r*HID+col];
          float xc = g_stage[8][(size_t)r*HID+col];
          float hr = g_stage[3][(size_t)r*HID+col];
          float hu = g_stage[4][(size_t)r*HID+col];
          float hc = g_stage[5][(size_t)r*HID+col];
          float rr = sigf(xr + p.bir[HID+col] + hr + p.bhr[HID+col]);
          float uu = sigf(xu + p.biu[HID+col] + hu + p.bhu[HID+col]);
          float cv = tanhf(xc + p.bic[HID+col] + rr*(hc + p.bhc[HID+col]));
          float h  = g_hbuf[cb][BH + (size_t)r*HID+col];
          hn[e] = (1.f-uu)*cv + uu*h;
          g_hbuf[nb][BH + (size_t)r*HID+col] = hn[e];
        }
        uint32_t hi, lo; splitH(hn[0], hn[1], hi, lo, SCL);
        g_hsp[nb][1][0][r][jc>>1] = hi;
        g_hsp[nb][1][1][r][jc>>1] = lo;
        g_X16[trow][jc>>1] = hi;     // single fp16 plane for out_gemm
      }
    }
    gridbar();
  }
}

// ---------------- l0x GEMM (split-bf16 3-pass, ldmatrix) ----------------
__global__ __launch_bounds__(256) void xproj_gemm(){
  int j = blockIdx.z;
  int m0 = blockIdx.y*128, n0 = blockIdx.x*128;
  __shared__ uint32_t sA[2][128][20];
  __shared__ uint32_t sW[2][128][20];
  int t = threadIdx.x, warp = t>>5, lane = t&31;
  int gid = lane>>2, tig = lane&3;
  int wr = warp>>1, wc = warp&1;
  int lr16 = lane&15, lws = (lane>>4)&1;
  int wr8 = lane&7,  ws4 = (lane>>3)&3;
  uint32_t aBase = smem_u32(&sA[0][0][0]);
  uint32_t wBase = smem_u32(&sW[0][0][0]);

  float acc[2][8][4];
  #pragma unroll
  for (int a=0;a<2;a++)
    #pragma unroll
    for (int b=0;b<8;b++)
      #pragma unroll
      for (int f=0;f<4;f++) acc[a][b][f]=0.f;

  uint4 pa[2][2], pw[2][2];
  auto ld = [&](int kc2){
    #pragma unroll
    for (int i=0;i<2;i++){
      int idx = t + i*256; int row = idx>>2, q4 = idx&3;
      pa[i][0] = *(const uint4*)&g_x0sp[0][m0+row][kc2+q4*4];
      pa[i][1] = *(const uint4*)&g_x0sp[1][m0+row][kc2+q4*4];
      pw[i][0] = *(const uint4*)&g_wxp[j][0][n0+row][kc2+q4*4];
      pw[i][1] = *(const uint4*)&g_wxp[j][1][n0+row][kc2+q4*4];
    }
  };
  ld(0);

  for (int kc2=0; kc2<KH; kc2+=16){
    #pragma unroll
    for (int i=0;i<2;i++){
      int idx = t + i*256; int row = idx>>2, q4 = idx&3;
      *(uint4*)&sA[0][row][q4*4] = pa[i][0];
      *(uint4*)&sA[1][row][q4*4] = pa[i][1];
      *(uint4*)&sW[0][row][q4*4] = pw[i][0];
      *(uint4*)&sW[1][row][q4*4] = pw[i][1];
    }
    __syncthreads();
    if (kc2+16 < KH) ld(kc2+16);

    uint32_t af[2][2][2][4];
    #pragma unroll
    for (int hl=0;hl<2;hl++)
      #pragma unroll
      for (int mt=0;mt<2;mt++)
        #pragma unroll
        for (int ks=0;ks<2;ks++)
          ldsm4(af[hl][mt][ks],
            aBase + 4u*((uint32_t)(hl*128 + wr*32 + mt*16 + lr16)*20u + ks*8 + lws*4));
    #pragma unroll
    for (int nt=0;nt<8;nt++){
      uint32_t wb[2][4];
      #pragma unroll
      for (int hl=0;hl<2;hl++)
        ldsm4(wb[hl],
          wBase + 4u*((uint32_t)(hl*128 + wc*64 + nt*8 + wr8)*20u + ws4*4));
      #pragma unroll
      for (int ks=0;ks<2;ks++){
        uint32_t bh0=wb[0][ks*2], bh1=wb[0][ks*2+1];
        uint32_t bl0=wb[1][ks*2], bl1=wb[1][ks*2+1];
        #pragma unroll
        for (int mt=0;mt<2;mt++){
          mma_bf16(acc[mt][nt], af[0][mt][ks][0],af[0][mt][ks][1],af[0][mt][ks][2],af[0][mt][ks][3], bl0,bl1);
          mma_bf16(acc[mt][nt], af[1][mt][ks][0],af[1][mt][ks][1],af[1][mt][ks][2],af[1][mt][ks][3], bh0,bh1);
          mma_bf16(acc[mt][nt], af[0][mt][ks][0],af[0][mt][ks][1],af[0][mt][ks][2],af[0][mt][ks][3], bh0,bh1);
        }
      }
    }
    __syncthreads();
  }
  float* C = g_l0x + (size_t)j*NROW*HID;
  #pragma unroll
  for (int mt=0;mt<2;mt++){
    int r0 = m0 + wr*32 + mt*16 + gid;
    #pragma unroll
    for (int nt=0;nt<8;nt++){
      int col = n0 + wc*64 + nt*8 + tig*2;
      C[(size_t)r0*HID + col  ]     = acc[mt][nt][0];
      C[(size_t)r0*HID + col+1]     = acc[mt][nt][1];
      C[(size_t)(r0+8)*HID + col  ] = acc[mt][nt][2];
      C[(size_t)(r0+8)*HID + col+1] = acc[mt][nt][3];
    }
  }
}

// ---------------- output GEMM (single-pass fp16, 2 CTAs/SM): logits = X @ Wout + bout -------
__global__ __launch_bounds__(256,2) void out_gemm(
    const float* __restrict__ bias, float* __restrict__ C)
{
  int m0 = blockIdx.y*128, n0 = blockIdx.x*128;
  __shared__ uint32_t sA[128][20];
  __shared__ uint32_t sW[128][20];
  int t = threadIdx.x, warp = t>>5, lane = t&31;
  int gid = lane>>2, tig = lane&3;
  int wr = warp>>1, wc = warp&1;
  int lr16 = lane&15, lws = (lane>>4)&1;
  int wr8 = lane&7,  ws4 = (lane>>3)&3;
  uint32_t aBase = smem_u32(&sA[0][0]);
  uint32_t wBase = smem_u32(&sW[0][0]);

  float acc[2][8][4];
  #pragma unroll
  for (int a=0;a<2;a++)
    #pragma unroll
    for (int b=0;b<8;b++)
      #pragma unroll
      for (int f=0;f<4;f++) acc[a][b][f]=0.f;

  uint4 pa[2], pw[2];
  auto ld = [&](int kc2){
    #pragma unroll
    for (int i=0;i<2;i++){
      int idx = t + i*256; int row = idx>>2, q4 = idx&3;
      pa[i] = *(const uint4*)&g_X16[m0+row][kc2+q4*4];
      pw[i] = *(const uint4*)&g_wo16[n0+row][kc2+q4*4];
    }
  };
  ld(0);

  for (int kc2=0; kc2<KH; kc2+=16){
    #pragma unroll
    for (int i=0;i<2;i++){
      int idx = t + i*256; int row = idx>>2, q4 = idx&3;
      *(uint4*)&sA[row][q4*4] = pa[i];
      *(uint4*)&sW[row][q4*4] = pw[i];
    }
    __syncthreads();
    if (kc2+16 < KH) ld(kc2+16);

    uint32_t af[2][2][4];
    #pragma unroll
    for (int mt=0;mt<2;mt++)
      #pragma unroll
      for (int ks=0;ks<2;ks++)
        ldsm4(af[mt][ks],
          aBase + 4u*((uint32_t)(wr*32 + mt*16 + lr16)*20u + ks*8 + lws*4));
    #pragma unroll
    for (int nt=0;nt<8;nt++){
      uint32_t wb[4];
      ldsm4(wb, wBase + 4u*((uint32_t)(wc*64 + nt*8 + wr8)*20u + ws4*4));
      #pragma unroll
      for (int ks=0;ks<2;ks++){
        uint32_t b0=wb[ks*2], b1=wb[ks*2+1];
        #pragma unroll
        for (int mt=0;mt<2;mt++)
          mma_f16(acc[mt][nt], af[mt][ks][0],af[mt][ks][1],af[mt][ks][2],af[mt][ks][3], b0,b1);
      }
    }
    __syncthreads();
  }
  #pragma unroll
  for (int mt=0;mt<2;mt++){
    int r0 = m0 + wr*32 + mt*16 + gid;
    #pragma unroll
    for (int nt=0;nt<8;nt++){
      int col = n0 + wc*64 + nt*8 + tig*2;
      float b0 = bias[col], b1 = bias[col+1];
      C[(size_t)r0*VOCAB + col  ]     = acc[mt][nt][0] + b0;
      C[(size_t)r0*VOCAB + col+1]     = acc[mt][nt][1] + b1;
      C[(size_t)(r0+8)*VOCAB + col  ] = acc[mt][nt][2] + b0;
      C[(size_t)(r0+8)*VOCAB + col+1] = acc[mt][nt][3] + b1;
    }
  }
}

extern "C" void kernel_launch(void* const* d_in, const int* in_sizes, int n_in,
                              void* d_out, int out_size) {
  P p;
  p.tok = (const int*)  d_in[0];
  p.hidden = (const float*)d_in[1];
  p.emb = (const float*)d_in[2];
  p.Wir = (const float*)d_in[3];  p.bir = (const float*)d_in[4];
  p.Whr = (const float*)d_in[5];  p.bhr = (const float*)d_in[6];
  p.Wiu = (const float*)d_in[7];  p.biu = (const float*)d_in[8];
  p.Whu = (const float*)d_in[9];  p.bhu = (const float*)d_in[10];
  p.Wic = (const float*)d_in[11]; p.bic = (const float*)d_in[12];
  p.Whc = (const float*)d_in[13]; p.bhc = (const float*)d_in[14];
  p.Wout= (const float*)d_in[15]; p.bout= (const float*)d_in[16];
  float* out = (float*)d_out;

  split_weights<<<dim3(HID/32, HID/32, 12), 256>>>(p);
  split_wout<<<dim3(VOCAB/32, HID/32), 256>>>(p);
  init_h_kernel<<<(NLAYERS*BH/2+255)/256, 256>>>(p);
  embed_split<<<(NROW*(EMBD/4)+255)/256, 256>>>(p);

  xproj_gemm<<<dim3(HID/128, NROW/128, 3), 256>>>();

  rec_persistent<<<NBLK, 256>>>(p);

  out_gemm<<<dim3(VOCAB/128, NROW/128), 256>>>(p.bout, out);
  copy_h_kernel<<<(NLAYERS*BH+255)/256, 256>>>(out + (size_t)SEQ*BATCH*VOCAB);
}

// round 17
// speedup vs baseline: 1.4037x; 1.4037x over previous
#include <cuda_runtime.h>
#include <cuda_bf16.h>
#include <cuda_fp16.h>
#include <cstdint>
#include <math.h>

#define EMBD 1536
#define HID 1536
#define KH (HID/2)                /* 768 packed k-pairs */
#define VOCAB 32000
#define NLAYERS 2
#define SEQ 64
#define BATCH 32
#define NROW (SEQ*BATCH)          /* 2048 */
#define BH (BATCH*HID)            /* 49152 */
#define NBLK 144
#define SCL 2048.0f
#define ISCL (1.0f/2048.0f)

// ---------------- device scratch ----------------
__device__ uint32_t g_wf[9][HID][KH];                 // recurrent weights fp16x2 single plane [n][k2]
__device__ uint32_t g_wxp[3][2][HID][KH];             // xproj weights bf16 hi/lo planes
__device__ uint32_t g_wo16[VOCAB][KH];                // Wout fp16x2 [v][k2]
__device__ uint32_t g_x0sp[2][NROW][KH];              // embeddings bf16 hi/lo
__device__ uint32_t g_X16[NROW][KH];                  // layer-1 outputs fp16 single plane
__device__ uint32_t g_hsp[2][NLAYERS][2][BATCH][KH];  // hidden fp16 hi + fp16 scaled-lo (ping-pong)
__device__ float    g_hbuf[2][NLAYERS*BH];            // fp32 hidden (ping-pong)
__device__ float    g_l0x[3*(size_t)NROW*HID];        // layer0 x-side projections
__device__ float    g_stage[9][(size_t)BH];           // pre-activations

__device__ unsigned g_bar_count = 0;
__device__ volatile unsigned g_bar_gen = 0;

struct P {
  const int* tok; const float* hidden; const float* emb;
  const float *Wir,*bir,*Whr,*bhr,*Wiu,*biu,*Whu,*bhu,*Wic,*bic,*Whc,*bhc,*Wout,*bout;
};

__device__ __forceinline__ float sigf(float x){ return 1.f/(1.f+expf(-x)); }

__device__ __forceinline__ uint32_t packbf(float a, float b){
  __nv_bfloat162 t; t.x = __float2bfloat16_rn(a); t.y = __float2bfloat16_rn(b);
  return *reinterpret_cast<uint32_t*>(&t);
}
__device__ __forceinline__ void split2(float a, float b, uint32_t& hi, uint32_t& lo){
  __nv_bfloat16 ha = __float2bfloat16_rn(a), hb = __float2bfloat16_rn(b);
  hi = packbf(__bfloat162float(ha), __bfloat162float(hb));
  lo = packbf(a - __bfloat162float(ha), b - __bfloat162float(hb));
}
__device__ __forceinline__ uint32_t packh(float a, float b){
  __half2 t = __floats2half2_rn(a, b);
  return *reinterpret_cast<uint32_t*>(&t);
}
__device__ __forceinline__ void splitH(float a, float b, uint32_t& hi, uint32_t& lo, float s){
  __half ha = __float2half_rn(a), hb = __float2half_rn(b);
  hi = packh(__half2float(ha), __half2float(hb));
  lo = packh((a - __half2float(ha))*s, (b - __half2float(hb))*s);
}
__device__ __forceinline__ void mma_bf16(float c[4],
    uint32_t a0,uint32_t a1,uint32_t a2,uint32_t a3, uint32_t b0,uint32_t b1){
  asm volatile(
    "mma.sync.aligned.m16n8k16.row.col.f32.bf16.bf16.f32 "
    "{%0,%1,%2,%3},{%4,%5,%6,%7},{%8,%9},{%0,%1,%2,%3};"
    : "+f"(c[0]),"+f"(c[1]),"+f"(c[2]),"+f"(c[3])
    : "r"(a0),"r"(a1),"r"(a2),"r"(a3),"r"(b0),"r"(b1));
}
__device__ __forceinline__ void mma_f16(float c[4],
    uint32_t a0,uint32_t a1,uint32_t a2,uint32_t a3, uint32_t b0,uint32_t b1){
  asm volatile(
    "mma.sync.aligned.m16n8k16.row.col.f32.f16.f16.f32 "
    "{%0,%1,%2,%3},{%4,%5,%6,%7},{%8,%9},{%0,%1,%2,%3};"
    : "+f"(c[0]),"+f"(c[1]),"+f"(c[2]),"+f"(c[3])
    : "r"(a0),"r"(a1),"r"(a2),"r"(a3),"r"(b0),"r"(b1));
}
__device__ __forceinline__ void ldsm4(uint32_t* r, uint32_t addr){
  asm volatile("ldmatrix.sync.aligned.m8n8.x4.shared.b16 {%0,%1,%2,%3}, [%4];"
    : "=r"(r[0]),"=r"(r[1]),"=r"(r[2]),"=r"(r[3]) : "r"(addr));
}
__device__ __forceinline__ uint32_t smem_u32(const void* p){
  uint32_t a;
  asm("{ .reg .u64 t; cvta.to.shared.u64 t, %1; cvt.u32.u64 %0, t; }" : "=r"(a) : "l"(p));
  return a;
}

// ---------------- grid barrier ----------------
__device__ __forceinline__ void gridbar(){
  __syncthreads();
  if (threadIdx.x==0){
    __threadfence();
    unsigned gen = g_bar_gen;
    if (atomicInc(&g_bar_count, NBLK-1) == (unsigned)(NBLK-1)){
      g_bar_gen = gen+1;
    } else {
      while (g_bar_gen == gen) {}
    }
    __threadfence();
  }
  __syncthreads();
}

// ---------------- one-time weight split ----------------
// mats 0-8 (recurrent): fp16 single plane; mats 9-11 (xproj): bf16 hi/lo
__global__ __launch_bounds__(256) void split_weights(P p){
  int mat = blockIdx.z;
  size_t HH = (size_t)HID*HID;
  const float* Wm;
  switch(mat){
    case 0: Wm=p.Whr;    break; case 1: Wm=p.Whu;    break; case 2:  Wm=p.Whc;    break;
    case 3: Wm=p.Whr+HH; break; case 4: Wm=p.Whu+HH; break; case 5:  Wm=p.Whc+HH; break;
    case 6: Wm=p.Wir+HH; break; case 7: Wm=p.Wiu+HH; break; case 8:  Wm=p.Wic+HH; break;
    case 9: Wm=p.Wir;    break; case 10:Wm=p.Wiu;    break; default: Wm=p.Wic;    break;
  }
  __shared__ float tile[32][33];
  int kc = blockIdx.y*32, n0 = blockIdx.x*32;
  int t = threadIdx.x;
  #pragma unroll
  for (int i=0;i<4;i++){
    int idx = t + i*256; int ky = idx>>5, nx = idx&31;
    tile[ky][nx] = Wm[(size_t)(kc+ky)*HID + n0+nx];
  }
  __syncthreads();
  #pragma unroll
  for (int i=0;i<2;i++){
    int slot = t + i*256; int ny = slot>>4, kx2 = slot&15;
    float a = tile[kx2*2][ny], b = tile[kx2*2+1][ny];
    if (mat < 9){
      g_wf[mat][n0+ny][(kc>>1)+kx2] = packh(a, b);
    } else {
      uint32_t hi, lo; split2(a, b, hi, lo);
      g_wxp[mat-9][0][n0+ny][(kc>>1)+kx2] = hi;
      g_wxp[mat-9][1][n0+ny][(kc>>1)+kx2] = lo;
    }
  }
}

// ---------------- Wout -> fp16 [v][k2] ----------------
__global__ __launch_bounds__(256) void split_wout(P p){
  __shared__ float tile[32][33];
  int kc = blockIdx.y*32, v0 = blockIdx.x*32;
  int t = threadIdx.x;
  #pragma unroll
  for (int i=0;i<4;i++){
    int idx = t + i*256; int ky = idx>>5, vx = idx&31;
    tile[ky][vx] = p.Wout[(size_t)(kc+ky)*VOCAB + v0+vx];
  }
  __syncthreads();
  #pragma unroll
  for (int i=0;i<2;i++){
    int slot = t + i*256; int vy = slot>>4, kx2 = slot&15;
    g_wo16[v0+vy][(kc>>1)+kx2] = packh(tile[kx2*2][vy], tile[kx2*2+1][vy]);
  }
}

// ---------------- embed + scale -> bf16 split ----------------
__global__ void embed_split(P p){
  int idx = blockIdx.x*blockDim.x + threadIdx.x;
  if (idx >= NROW*(EMBD/4)) return;
  int row = idx/(EMBD/4), e4 = idx%(EMBD/4);
  float4 v = ((const float4*)p.emb)[(size_t)p.tok[row]*(EMBD/4)+e4];
  float s = sqrtf((float)EMBD);
  uint32_t h0,l0,h1,l1;
  split2(v.x*s, v.y*s, h0, l0);
  split2(v.z*s, v.w*s, h1, l1);
  g_x0sp[0][row][e4*2]   = h0; g_x0sp[0][row][e4*2+1] = h1;
  g_x0sp[1][row][e4*2]   = l0; g_x0sp[1][row][e4*2+1] = l1;
}

__global__ void init_h_kernel(P p){
  int i = blockIdx.x*blockDim.x + threadIdx.x;
  if (i >= NLAYERS*BH/2) return;
  int e = i*2;
  float v0 = p.hidden[e], v1 = p.hidden[e+1];
  g_hbuf[0][e] = v0; g_hbuf[0][e+1] = v1;
  int layer = e / BH, rem = e % BH;
  int r = rem / HID, k = rem % HID;
  uint32_t hi, lo; splitH(v0, v1, hi, lo, SCL);
  g_hsp[0][layer][0][r][k>>1] = hi;
  g_hsp[0][layer][1][r][k>>1] = lo;
}
__global__ void copy_h_kernel(float* out){
  int i = blockIdx.x*blockDim.x + threadIdx.x;
  if (i < NLAYERS*BH) out[i] = g_hbuf[0][i];
}

// ---------------- persistent recurrence: fp16 2-pass ----------------
__global__ __launch_bounds__(256) void rec_persistent(P p){
  __shared__ union SMu {
    struct { uint32_t A[2][2][32][20]; uint32_t W[2][64][20]; } p1;
    struct { uint32_t A[2][2][2][32][20]; uint32_t W[2][2][32][20]; } p2;
    float red[128*8];
  } sm;

  int blk = blockIdx.x, tid = threadIdx.x;
  int warp = tid>>5, lane = tid&31, gid = lane>>2, tig = lane&3;
  int lr16 = lane&15, lws = (lane>>4)&1;
  int wr8 = lane&7,  ws4 = (lane>>3)&3;

  for (int t=0; t<SEQ; t++){
    int cb = t&1, nb = cb^1;

    // ======== phase 1 ========
    {
      int mat = blk/24, n0 = (blk%24)*64;
      int layer = mat/3;
      const uint32_t* Ah = &g_hsp[cb][layer][0][0][0];
      const uint32_t* Al = &g_hsp[cb][layer][1][0][0];
      float accH[2][4] = {}, accL[2][4] = {};
      int c0 = warp*8;
      uint32_t aBase = smem_u32(&sm.p1.A[0][0][0][0]);
      uint32_t wBase = smem_u32(&sm.p1.W[0][0][0]);

      int a_pl = tid>>7, a_row = (tid>>2)&31, a_q = tid&3;
      const uint32_t* Aside = a_pl ? Al : Ah;
      int w_col = tid>>2, w_q = tid&3;
      uint4 pa, pw;
      auto ld = [&](int kc2){
        pa = *(const uint4*)&Aside[a_row*KH + kc2 + a_q*4];
        pw = *(const uint4*)&g_wf[mat][n0+w_col][kc2 + w_q*4];
      };
      auto stbuf = [&](int b){
        *(uint4*)&sm.p1.A[b][a_pl][a_row][a_q*4] = pa;
        *(uint4*)&sm.p1.W[b][w_col][w_q*4] = pw;
      };
      ld(0); stbuf(0); __syncthreads();
      for (int s=0; s<48; s++){
        int cur = s&1;
        if (s<47) ld((s+1)*16);
        uint32_t af[2][2][2][4];
        #pragma unroll
        for (int pl=0;pl<2;pl++)
          #pragma unroll
          for (int mt=0;mt<2;mt++)
            #pragma unroll
            for (int ks=0;ks<2;ks++)
              ldsm4(af[pl][mt][ks],
                aBase + 4u*((uint32_t)(((cur*2+pl)*32) + mt*16 + lr16)*20u + ks*8 + lws*4));
        uint32_t wb[4];
        ldsm4(wb, wBase + 4u*((uint32_t)(cur*64 + c0 + wr8)*20u + ws4*4));
        #pragma unroll
        for (int ks=0;ks<2;ks++){
          uint32_t b0=wb[ks*2], b1=wb[ks*2+1];
          #pragma unroll
          for (int mt=0;mt<2;mt++){
            mma_f16(accH[mt], af[0][mt][ks][0],af[0][mt][ks][1],af[0][mt][ks][2],af[0][mt][ks][3], b0,b1);
            mma_f16(accL[mt], af[1][mt][ks][0],af[1][mt][ks][1],af[1][mt][ks][2],af[1][mt][ks][3], b0,b1);
          }
        }
        if (s<47){ stbuf(cur^1); __syncthreads(); }
      }
      int col = n0 + warp*8 + tig*2;
      #pragma unroll
      for (int mt=0; mt<2; mt++){
        int r = mt*16+gid;
        g_stage[mat][(size_t)r*HID+col]       = accH[mt][0] + accL[mt][0]*ISCL;
        g_stage[mat][(size_t)r*HID+col+1]     = accH[mt][1] + accL[mt][1]*ISCL;
        g_stage[mat][(size_t)(r+8)*HID+col]   = accH[mt][2] + accL[mt][2]*ISCL;
        g_stage[mat][(size_t)(r+8)*HID+col+1] = accH[mt][3] + accL[mt][3]*ISCL;
      }
    }
    gridbar();

    // ======== G0 ========
    {
      int pr = blk*256 + tid;
      if (pr < BH/2){
        int r = pr/(HID/2), jc = (pr%(HID/2))*2;
        size_t trow = (size_t)t*BATCH + r;
        float hn[2];
        #pragma unroll
        for (int e=0;e<2;e++){
          int col = jc+e;
          float xr = g_l0x[0*(size_t)NROW*HID + trow*HID + col];
          float xu = g_l0x[1*(size_t)NROW*HID + trow*HID + col];
          float xc = g_l0x[2*(size_t)NROW*HID + trow*HID + col];
          float hr = g_stage[0][(size_t)r*HID+col];
          float hu = g_stage[1][(size_t)r*HID+col];
          float hc = g_stage[2][(size_t)r*HID+col];
          float rr = sigf(xr + p.bir[col] + hr + p.bhr[col]);
          float uu = sigf(xu + p.biu[col] + hu + p.bhu[col]);
          float cv = tanhf(xc + p.bic[col] + rr*(hc + p.bhc[col]));
          float h  = g_hbuf[cb][(size_t)r*HID+col];
          hn[e] = (1.f-uu)*cv + uu*h;
          g_hbuf[nb][(size_t)r*HID+col] = hn[e];
        }
        uint32_t hi, lo; splitH(hn[0], hn[1], hi, lo, SCL);
        g_hsp[nb][0][0][r][jc>>1] = hi;
        g_hsp[nb][0][1][r][jc>>1] = lo;
      }
    }
    gridbar();

    // ======== phase 2 ========
    {
      int mat = 6 + blk/48, n0 = (blk%48)*32;
      const uint32_t* Ah = &g_hsp[nb][0][0][0][0];
      const uint32_t* Al = &g_hsp[nb][0][1][0][0];
      float accH[2][4] = {}, accL[2][4] = {};
      int half = warp>>2, cg = warp&3;
      int c0 = cg*8;
      uint32_t aBase = smem_u32(&sm.p2.A[0][0][0][0][0]);
      uint32_t wBase = smem_u32(&sm.p2.W[0][0][0][0]);

      uint4 pa[2], pw;
      auto ld2 = [&](int s16){
        #pragma unroll
        for (int i=0;i<2;i++){
          int idx = tid + i*256;
          int pl = idx>>8, hf = (idx>>7)&1, row = (idx>>2)&31, q = idx&3;
          const uint32_t* As = pl ? Al : Ah;
          pa[i] = *(const uint4*)&As[row*KH + hf*(KH/2) + s16 + q*4];
        }
        int hf = tid>>7, row = (tid>>2)&31, q = tid&3;
        pw = *(const uint4*)&g_wf[mat][n0+row][hf*(KH/2) + s16 + q*4];
      };
      auto stbuf2 = [&](int b){
        #pragma unroll
        for (int i=0;i<2;i++){
          int idx = tid + i*256;
          int pl = idx>>8, hf = (idx>>7)&1, row = (idx>>2)&31, q = idx&3;
          *(uint4*)&sm.p2.A[b][pl][hf][row][q*4] = pa[i];
        }
        int hf = tid>>7, row = (tid>>2)&31, q = tid&3;
        *(uint4*)&sm.p2.W[b][hf][row][q*4] = pw;
      };
      ld2(0); stbuf2(0); __syncthreads();
      for (int s=0; s<24; s++){
        int cur = s&1;
        if (s<23) ld2((s+1)*16);
        uint32_t af[2][2][2][4];
        #pragma unroll
        for (int pl=0;pl<2;pl++)
          #pragma unroll
          for (int mt=0;mt<2;mt++)
            #pragma unroll
            for (int ks=0;ks<2;ks++)
              ldsm4(af[pl][mt][ks],
                aBase + 4u*((uint32_t)((((cur*2+pl)*2+half)*32) + mt*16 + lr16)*20u + ks*8 + lws*4));
        uint32_t wb[4];
        ldsm4(wb, wBase + 4u*((uint32_t)((cur*2+half)*32 + c0 + wr8)*20u + ws4*4));
        #pragma unroll
        for (int ks=0;ks<2;ks++){
          uint32_t b0=wb[ks*2], b1=wb[ks*2+1];
          #pragma unroll
          for (int mt=0;mt<2;mt++){
            mma_f16(accH[mt], af[0][mt][ks][0],af[0][mt][ks][1],af[0][mt][ks][2],af[0][mt][ks][3], b0,b1);
            mma_f16(accL[mt], af[1][mt][ks][0],af[1][mt][ks][1],af[1][mt][ks][2],af[1][mt][ks][3], b0,b1);
          }
        }
        if (s<23){ stbuf2(cur^1); __syncthreads(); }
      }
      float acc[2][4];
      #pragma unroll
      for (int mt=0;mt<2;mt++)
        #pragma unroll
        for (int f=0;f<4;f++) acc[mt][f] = accH[mt][f] + accL[mt][f]*ISCL;
      __syncthreads();
      if (half==1){
        #pragma unroll
        for (int mt=0; mt<2; mt++)
          #pragma unroll
          for (int f=0; f<4; f++)
            sm.red[(tid&127)*8 + mt*4+f] = acc[mt][f];
      }
      __syncthreads();
      if (half==0){
        #pragma unroll
        for (int mt=0; mt<2; mt++)
          #pragma unroll
          for (int f=0; f<4; f++)
            acc[mt][f] += sm.red[(tid&127)*8 + mt*4+f];
        int col = n0 + cg*8 + tig*2;
        #pragma unroll
        for (int mt=0; mt<2; mt++){
          int r = mt*16+gid;
          g_stage[mat][(size_t)r*HID+col]       = acc[mt][0];
          g_stage[mat][(size_t)r*HID+col+1]     = acc[mt][1];
          g_stage[mat][(size_t)(r+8)*HID+col]   = acc[mt][2];
          g_stage[mat][(size_t)(r+8)*HID+col+1] = acc[mt][3];
        }
      }
    }
    gridbar();

    // ======== G1 ========
    {
      int pr = blk*256 + tid;
      if (pr < BH/2){
        int r = pr/(HID/2), jc = (pr%(HID/2))*2;
        size_t trow = (size_t)t*BATCH + r;
        float hn[2];
        #pragma unroll
        for (int e=0;e<2;e++){
          int col = jc+e;
          float xr = g_stage[6][(size_t)r*HID+col];
          float xu = g_stage[7][(size_t)r*HID+col];
          float xc = g_stage[8][(size_t)r*HID+col];
          float hr = g_stage[3][(size_t)r*HID+col];
          float hu = g_stage[4][(size_t)r*HID+col];
          float hc = g_stage[5][(size_t)r*HID+col];
          float rr = sigf(xr + p.bir[HID+col] + hr + p.bhr[HID+col]);
          float uu = sigf(xu + p.biu[HID+col] + hu + p.bhu[HID+col]);
          float cv = tanhf(xc + p.bic[HID+col] + rr*(hc + p.bhc[HID+col]));
          float h  = g_hbuf[cb][BH + (size_t)r*HID+col];
          hn[e] = (1.f-uu)*cv + uu*h;
          g_hbuf[nb][BH + (size_t)r*HID+col] = hn[e];
        }
        uint32_t hi, lo; splitH(hn[0], hn[1], hi, lo, SCL);
        g_hsp[nb][1][0][r][jc>>1] = hi;
        g_hsp[nb][1][1][r][jc>>1] = lo;
        g_X16[trow][jc>>1] = hi;     // single fp16 plane for out_gemm
      }
    }
    gridbar();
  }
}

// ---------------- l0x GEMM (split-bf16 3-pass, ldmatrix) ----------------
__global__ __launch_bounds__(256) void xproj_gemm(){
  int j = blockIdx.z;
  int m0 = blockIdx.y*128, n0 = blockIdx.x*128;
  __shared__ uint32_t sA[2][128][20];
  __shared__ uint32_t sW[2][128][20];
  int t = threadIdx.x, warp = t>>5, lane = t&31;
  int gid = lane>>2, tig = lane&3;
  int wr = warp>>1, wc = warp&1;
  int lr16 = lane&15, lws = (lane>>4)&1;
  int wr8 = lane&7,  ws4 = (lane>>3)&3;
  uint32_t aBase = smem_u32(&sA[0][0][0]);
  uint32_t wBase = smem_u32(&sW[0][0][0]);

  float acc[2][8][4];
  #pragma unroll
  for (int a=0;a<2;a++)
    #pragma unroll
    for (int b=0;b<8;b++)
      #pragma unroll
      for (int f=0;f<4;f++) acc[a][b][f]=0.f;

  uint4 pa[2][2], pw[2][2];
  auto ld = [&](int kc2){
    #pragma unroll
    for (int i=0;i<2;i++){
      int idx = t + i*256; int row = idx>>2, q4 = idx&3;
      pa[i][0] = *(const uint4*)&g_x0sp[0][m0+row][kc2+q4*4];
      pa[i][1] = *(const uint4*)&g_x0sp[1][m0+row][kc2+q4*4];
      pw[i][0] = *(const uint4*)&g_wxp[j][0][n0+row][kc2+q4*4];
      pw[i][1] = *(const uint4*)&g_wxp[j][1][n0+row][kc2+q4*4];
    }
  };
  ld(0);

  for (int kc2=0; kc2<KH; kc2+=16){
    #pragma unroll
    for (int i=0;i<2;i++){
      int idx = t + i*256; int row = idx>>2, q4 = idx&3;
      *(uint4*)&sA[0][row][q4*4] = pa[i][0];
      *(uint4*)&sA[1][row][q4*4] = pa[i][1];
      *(uint4*)&sW[0][row][q4*4] = pw[i][0];
      *(uint4*)&sW[1][row][q4*4] = pw[i][1];
    }
    __syncthreads();
    if (kc2+16 < KH) ld(kc2+16);

    uint32_t af[2][2][2][4];
    #pragma unroll
    for (int hl=0;hl<2;hl++)
      #pragma unroll
      for (int mt=0;mt<2;mt++)
        #pragma unroll
        for (int ks=0;ks<2;ks++)
          ldsm4(af[hl][mt][ks],
            aBase + 4u*((uint32_t)(hl*128 + wr*32 + mt*16 + lr16)*20u + ks*8 + lws*4));
    #pragma unroll
    for (int nt=0;nt<8;nt++){
      uint32_t wb[2][4];
      #pragma unroll
      for (int hl=0;hl<2;hl++)
        ldsm4(wb[hl],
          wBase + 4u*((uint32_t)(hl*128 + wc*64 + nt*8 + wr8)*20u + ws4*4));
      #pragma unroll
      for (int ks=0;ks<2;ks++){
        uint32_t bh0=wb[0][ks*2], bh1=wb[0][ks*2+1];
        uint32_t bl0=wb[1][ks*2], bl1=wb[1][ks*2+1];
        #pragma unroll
        for (int mt=0;mt<2;mt++){
          mma_bf16(acc[mt][nt], af[0][mt][ks][0],af[0][mt][ks][1],af[0][mt][ks][2],af[0][mt][ks][3], bl0,bl1);
          mma_bf16(acc[mt][nt], af[1][mt][ks][0],af[1][mt][ks][1],af[1][mt][ks][2],af[1][mt][ks][3], bh0,bh1);
          mma_bf16(acc[mt][nt], af[0][mt][ks][0],af[0][mt][ks][1],af[0][mt][ks][2],af[0][mt][ks][3], bh0,bh1);
        }
      }
    }
    __syncthreads();
  }
  float* C = g_l0x + (size_t)j*NROW*HID;
  #pragma unroll
  for (int mt=0;mt<2;mt++){
    int r0 = m0 + wr*32 + mt*16 + gid;
    #pragma unroll
    for (int nt=0;nt<8;nt++){
      int col = n0 + wc*64 + nt*8 + tig*2;
      C[(size_t)r0*HID + col  ]     = acc[mt][nt][0];
      C[(size_t)r0*HID + col+1]     = acc[mt][nt][1];
      C[(size_t)(r0+8)*HID + col  ] = acc[mt][nt][2];
      C[(size_t)(r0+8)*HID + col+1] = acc[mt][nt][3];
    }
  }
}

// ---------------- output GEMM (single-pass fp16): logits = X @ Wout + bout ----------------
__global__ __launch_bounds__(256) void out_gemm(
    const float* __restrict__ bias, float* __restrict__ C)
{
  int m0 = blockIdx.y*128, n0 = blockIdx.x*128;
  __shared__ uint32_t sA[128][20];
  __shared__ uint32_t sW[128][20];
  int t = threadIdx.x, warp = t>>5, lane = t&31;
  int gid = lane>>2, tig = lane&3;
  int wr = warp>>1, wc = warp&1;
  int lr16 = lane&15, lws = (lane>>4)&1;
  int wr8 = lane&7,  ws4 = (lane>>3)&3;
  uint32_t aBase = smem_u32(&sA[0][0]);
  uint32_t wBase = smem_u32(&sW[0][0]);

  float acc[2][8][4];
  #pragma unroll
  for (int a=0;a<2;a++)
    #pragma unroll
    for (int b=0;b<8;b++)
      #pragma unroll
      for (int f=0;f<4;f++) acc[a][b][f]=0.f;

  uint4 pa[2], pw[2];
  auto ld = [&](int kc2){
    #pragma unroll
    for (int i=0;i<2;i++){
      int idx = t + i*256; int row = idx>>2, q4 = idx&3;
      pa[i] = *(const uint4*)&g_X16[m0+row][kc2+q4*4];
      pw[i] = *(const uint4*)&g_wo16[n0+row][kc2+q4*4];
    }
  };
  ld(0);

  for (int kc2=0; kc2<KH; kc2+=16){
    #pragma unroll
    for (int i=0;i<2;i++){
      int idx = t + i*256; int row = idx>>2, q4 = idx&3;
      *(uint4*)&sA[row][q4*4] = pa[i];
      *(uint4*)&sW[row][q4*4] = pw[i];
    }
    __syncthreads();
    if (kc2+16 < KH) ld(kc2+16);

    uint32_t af[2][2][4];
    #pragma unroll
    for (int mt=0;mt<2;mt++)
      #pragma unroll
      for (int ks=0;ks<2;ks++)
        ldsm4(af[mt][ks],
          aBase + 4u*((uint32_t)(wr*32 + mt*16 + lr16)*20u + ks*8 + lws*4));
    #pragma unroll
    for (int nt=0;nt<8;nt++){
      uint32_t wb[4];
      ldsm4(wb, wBase + 4u*((uint32_t)(wc*64 + nt*8 + wr8)*20u + ws4*4));
      #pragma unroll
      for (int ks=0;ks<2;ks++){
        uint32_t b0=wb[ks*2], b1=wb[ks*2+1];
        #pragma unroll
        for (int mt=0;mt<2;mt++)
          mma_f16(acc[mt][nt], af[mt][ks][0],af[mt][ks][1],af[mt][ks][2],af[mt][ks][3], b0,b1);
      }
    }
    __syncthreads();
  }
  #pragma unroll
  for (int mt=0;mt<2;mt++){
    int r0 = m0 + wr*32 + mt*16 + gid;
    #pragma unroll
    for (int nt=0;nt<8;nt++){
      int col = n0 + wc*64 + nt*8 + tig*2;
      float b0 = bias[col], b1 = bias[col+1];
      C[(size_t)r0*VOCAB + col  ]     = acc[mt][nt][0] + b0;
      C[(size_t)r0*VOCAB + col+1]     = acc[mt][nt][1] + b1;
      C[(size_t)(r0+8)*VOCAB + col  ] = acc[mt][nt][2] + b0;
      C[(size_t)(r0+8)*VOCAB + col+1] = acc[mt][nt][3] + b1;
    }
  }
}

extern "C" void kernel_launch(void* const* d_in, const int* in_sizes, int n_in,
                              void* d_out, int out_size) {
  P p;
  p.tok = (const int*)  d_in[0];
  p.hidden = (const float*)d_in[1];
  p.emb = (const float*)d_in[2];
  p.Wir = (const float*)d_in[3];  p.bir = (const float*)d_in[4];
  p.Whr = (const float*)d_in[5];  p.bhr = (const float*)d_in[6];
  p.Wiu = (const float*)d_in[7];  p.biu = (const float*)d_in[8];
  p.Whu = (const float*)d_in[9];  p.bhu = (const float*)d_in[10];
  p.Wic = (const float*)d_in[11]; p.bic = (const float*)d_in[12];
  p.Whc = (const float*)d_in[13]; p.bhc = (const float*)d_in[14];
  p.Wout= (const float*)d_in[15]; p.bout= (const float*)d_in[16];
  float* out = (float*)d_out;

  split_weights<<<dim3(HID/32, HID/32, 12), 256>>>(p);
  split_wout<<<dim3(VOCAB/32, HID/32), 256>>>(p);
  init_h_kernel<<<(NLAYERS*BH/2+255)/256, 256>>>(p);
  embed_split<<<(NROW*(EMBD/4)+255)/256, 256>>>(p);

  xproj_gemm<<<dim3(HID/128, NROW/128, 3), 256>>>();

  rec_persistent<<<NBLK, 256>>>(p);

  out_gemm<<<dim3(VOCAB/128, NROW/128), 256>>>(p.bout, out);
  copy_h_kernel<<<(NLAYERS*BH+255)/256, 256>>>(out + (size_t)SEQ*BATCH*VOCAB);
}